// round 12
// baseline (speedup 1.0000x reference)
#include <cuda_runtime.h>
#include <math.h>

#define NN 200000
#define NE 800000
#define NG 8192
#define HD 128
#define ENT 64          // nodes per block tile: encoder
#define MNT 128         // nodes per block tile: node MLP (512 thr, f32x2 path)

typedef unsigned long long ull;

// ---------------- scratch (static device allocations; no cudaMalloc) ----------
__device__ float g_h[(size_t)NN * HD];     // node features          (~102 MB)
__device__ float g_z[(size_t)NN * HD];     // h + scattered messages (~102 MB)
__device__ float g_sums[NG * HD];          // pooled sums
__device__ float g_cnt[NG];                // pooled counts

__device__ __forceinline__ void red_add_v4(float* p, float4 v) {
    asm volatile("red.global.add.v4.f32 [%0], {%1,%2,%3,%4};"
                 :: "l"(p), "f"(v.x), "f"(v.y), "f"(v.z), "f"(v.w) : "memory");
}

// -------- packed f32x2 helpers (Blackwell FFMA2; ptxas won't auto-fuse) -------
__device__ __forceinline__ ull fma2(ull a, ull b, ull c) {
    ull d;
    asm("fma.rn.f32x2 %0, %1, %2, %3;" : "=l"(d) : "l"(a), "l"(b), "l"(c));
    return d;
}
__device__ __forceinline__ ull pack2(float lo, float hi) {
    ull d;
    asm("mov.b64 %0, {%1, %2};" : "=l"(d) : "f"(lo), "f"(hi));
    return d;
}
__device__ __forceinline__ void unpack2(ull v, float& lo, float& hi) {
    asm("mov.b64 {%0, %1}, %2;" : "=f"(lo), "=f"(hi) : "l"(v));
}

// ---------------- encoder: h = x @ W_enc + b_enc  (K=78); writes g_h AND g_z --
__global__ void __launch_bounds__(128, 1)
encoder_kernel(const float* __restrict__ x,
               const float* __restrict__ W,
               const float* __restrict__ b) {
    extern __shared__ float sm[];
    float* Ws = sm;              // 78*128
    float* xt = Ws + 78 * HD;    // 78*ENT, k-major
    const int tid = threadIdx.x;
    const int node0 = blockIdx.x * ENT;

    const float4* Wg4 = (const float4*)W;
    float4* Ws4 = (float4*)Ws;
    for (int i = tid; i < 78 * (HD / 4); i += 128) Ws4[i] = Wg4[i];
    for (int idx = tid; idx < 78 * ENT; idx += 128) {
        int m = idx / 78, k = idx - m * 78;
        xt[k * ENT + m] = x[(size_t)(node0 + m) * 78 + k];
    }
    __syncthreads();

    const int r = tid >> 4, c = tid & 15;
    float acc[8][8];
#pragma unroll
    for (int j = 0; j < 8; j++) {
        float bb = b[c * 8 + j];
#pragma unroll
        for (int i = 0; i < 8; i++) acc[i][j] = bb;
    }
#pragma unroll 2
    for (int k = 0; k < 78; k++) {
        float4 a0 = *(float4*)&xt[k * ENT + r * 8];
        float4 a1 = *(float4*)&xt[k * ENT + r * 8 + 4];
        float4 w0 = *(float4*)&Ws[k * HD + c * 8];
        float4 w1 = *(float4*)&Ws[k * HD + c * 8 + 4];
        float a[8] = {a0.x, a0.y, a0.z, a0.w, a1.x, a1.y, a1.z, a1.w};
        float w[8] = {w0.x, w0.y, w0.z, w0.w, w1.x, w1.y, w1.z, w1.w};
#pragma unroll
        for (int i = 0; i < 8; i++)
#pragma unroll
            for (int j = 0; j < 8; j++) acc[i][j] += a[i] * w[j];
    }
#pragma unroll
    for (int i = 0; i < 8; i++) {
        float4 o0 = {acc[i][0], acc[i][1], acc[i][2], acc[i][3]};
        float4 o1 = {acc[i][4], acc[i][5], acc[i][6], acc[i][7]};
        size_t off = (size_t)(node0 + r * 8 + i) * HD + c * 8;
        *(float4*)(g_h + off)     = o0;
        *(float4*)(g_h + off + 4) = o1;
        *(float4*)(g_z + off)     = o0;   // pre-init scatter accumulator
        *(float4*)(g_z + off + 4) = o1;
    }
}

// ---------------- edge: m = relu(h[src] + ea@We + be); red-add into z[dst] ----
#define EPW 16
__global__ void __launch_bounds__(256)
edge_kernel(const int* __restrict__ src, const int* __restrict__ dst,
            const float* __restrict__ ea,
            const float* __restrict__ We, const float* __restrict__ be) {
    __shared__ float Wes[10 * HD];
    for (int i = threadIdx.x; i < 10 * HD; i += 256) Wes[i] = We[i];
    __syncthreads();

    const int lane = threadIdx.x & 31;
    const int warp = threadIdx.x >> 5;
    const int e0 = (blockIdx.x * 8 + warp) * EPW;
    const float4 bev = *(const float4*)&be[lane * 4];
    const float4* We4 = (const float4*)Wes;

    float4 wreg[10];
#pragma unroll
    for (int k = 0; k < 10; k++) wreg[k] = We4[k * 32 + lane];

    // prime pipeline
    int s = src[e0], d = dst[e0];
    float av = (lane < 10) ? ea[(size_t)e0 * 10 + lane] : 0.f;
    float4 hv = *(const float4*)(g_h + (size_t)s * HD + lane * 4);

    for (int t = 0; t < EPW; t++) {
        int s2 = 0, d2 = 0; float av2 = 0.f; float4 hv2 = hv;
        if (t + 1 < EPW) {
            int e2 = e0 + t + 1;
            s2 = src[e2]; d2 = dst[e2];
            av2 = (lane < 10) ? ea[(size_t)e2 * 10 + lane] : 0.f;
            hv2 = *(const float4*)(g_h + (size_t)s2 * HD + lane * 4);
        }
        float4 acc = bev;
#pragma unroll
        for (int k = 0; k < 10; k++) {
            float a = __shfl_sync(0xffffffffu, av, k);
            acc.x += a * wreg[k].x; acc.y += a * wreg[k].y;
            acc.z += a * wreg[k].z; acc.w += a * wreg[k].w;
        }
        float4 m;
        m.x = fmaxf(hv.x + acc.x, 0.f);
        m.y = fmaxf(hv.y + acc.y, 0.f);
        m.z = fmaxf(hv.z + acc.z, 0.f);
        m.w = fmaxf(hv.w + acc.w, 0.f);
        red_add_v4(g_z + (size_t)d * HD + lane * 4, m);
        s = s2; d = d2; av = av2; hv = hv2;
    }
}

// ---------------- node MLP: h = relu(BN(relu(z@W1+b1)@W2+b2)) -----------------
// 512 threads, 128-node tile, 4x8 micro-tiles, packed fma.rn.f32x2 math.
// Weights duplicated in smem (Wd[k][2j]=Wd[k][2j+1]=W[k][j]) so both FFMA2
// operands come packed straight from 128-bit LDS. Writes g_h AND g_z.
__global__ void __launch_bounds__(512, 1)
node_mlp_kernel(const float* __restrict__ W1, const float* __restrict__ b1,
                const float* __restrict__ W2, const float* __restrict__ b2,
                const float* __restrict__ gamma, const float* __restrict__ beta,
                int write_z) {
    extern __shared__ float sm[];
    float* Wd = sm;               // 128 x 256 duplicated weights (128 KB)
    float* zt = sm + 32768;       // 128 x 128 tile, k-major (64 KB)
    const int tid = threadIdx.x;
    const int node0 = blockIdx.x * MNT;

    const float4* W1g = (const float4*)W1;
    const float4* W2g = (const float4*)W2;
    // stage W1 duplicated
    for (int i = tid; i < 4096; i += 512) {
        float4 w = W1g[i];
        int k = i >> 5, n4 = i & 31;
        ((float4*)Wd)[k * 64 + n4 * 2]     = make_float4(w.x, w.x, w.y, w.y);
        ((float4*)Wd)[k * 64 + n4 * 2 + 1] = make_float4(w.z, w.z, w.w, w.w);
    }
    // stage z tile transposed (k-major); clamp rows past NN
    {
        int k4 = tid & 31, m0 = tid >> 5;   // m0 in 0..15
        for (int mm = m0; mm < MNT; mm += 16) {
            int row = node0 + mm; if (row >= NN) row = NN - 1;
            float4 v = *(const float4*)(g_z + (size_t)row * HD + k4 * 4);
            zt[(k4 * 4 + 0) * MNT + mm] = v.x;
            zt[(k4 * 4 + 1) * MNT + mm] = v.y;
            zt[(k4 * 4 + 2) * MNT + mm] = v.z;
            zt[(k4 * 4 + 3) * MNT + mm] = v.w;
        }
    }
    __syncthreads();

    const int r = tid >> 4, c = tid & 15;   // 32 x 16 grid of 4x8 micro-tiles
    ull acc2[2][8];                         // [i-pair][j]; pair over M dim
#pragma unroll
    for (int j = 0; j < 8; j++) {
        float bb = b1[c * 8 + j];
        ull pb = pack2(bb, bb);
        acc2[0][j] = pb; acc2[1][j] = pb;
    }
#pragma unroll 4
    for (int k = 0; k < HD; k++) {
        ulonglong2 ap = *(const ulonglong2*)&zt[k * MNT + r * 4];
        const ulonglong2* wp = (const ulonglong2*)&Wd[k * 256 + c * 16];
        ulonglong2 w0 = wp[0], w1 = wp[1], w2 = wp[2], w3 = wp[3];
        ull wd[8] = {w0.x, w0.y, w1.x, w1.y, w2.x, w2.y, w3.x, w3.y};
#pragma unroll
        for (int j = 0; j < 8; j++) {
            acc2[0][j] = fma2(ap.x, wd[j], acc2[0][j]);
            acc2[1][j] = fma2(ap.y, wd[j], acc2[1][j]);
        }
    }
    __syncthreads();   // all GEMM1 reads of zt / Wd done

    // relu(t) stored transposed back into zt (k-major over the j dimension)
#pragma unroll
    for (int j = 0; j < 8; j++) {
        float v0, v1, v2, v3;
        unpack2(acc2[0][j], v0, v1);
        unpack2(acc2[1][j], v2, v3);
        *(float4*)&zt[(c * 8 + j) * MNT + r * 4] =
            make_float4(fmaxf(v0, 0.f), fmaxf(v1, 0.f), fmaxf(v2, 0.f), fmaxf(v3, 0.f));
    }
    // stage W2 duplicated
    for (int i = tid; i < 4096; i += 512) {
        float4 w = W2g[i];
        int k = i >> 5, n4 = i & 31;
        ((float4*)Wd)[k * 64 + n4 * 2]     = make_float4(w.x, w.x, w.y, w.y);
        ((float4*)Wd)[k * 64 + n4 * 2 + 1] = make_float4(w.z, w.z, w.w, w.w);
    }
    __syncthreads();

#pragma unroll
    for (int j = 0; j < 8; j++) {
        float bb = b2[c * 8 + j];
        ull pb = pack2(bb, bb);
        acc2[0][j] = pb; acc2[1][j] = pb;
    }
#pragma unroll 4
    for (int k = 0; k < HD; k++) {
        ulonglong2 ap = *(const ulonglong2*)&zt[k * MNT + r * 4];
        const ulonglong2* wp = (const ulonglong2*)&Wd[k * 256 + c * 16];
        ulonglong2 w0 = wp[0], w1 = wp[1], w2 = wp[2], w3 = wp[3];
        ull wd[8] = {w0.x, w0.y, w1.x, w1.y, w2.x, w2.y, w3.x, w3.y};
#pragma unroll
        for (int j = 0; j < 8; j++) {
            acc2[0][j] = fma2(ap.x, wd[j], acc2[0][j]);
            acc2[1][j] = fma2(ap.y, wd[j], acc2[1][j]);
        }
    }

    const float inv_std = rsqrtf(1.0f + 1e-5f);
    float sc[8], bt[8];
#pragma unroll
    for (int j = 0; j < 8; j++) {
        sc[j] = gamma[c * 8 + j] * inv_std;
        bt[j] = beta[c * 8 + j];
    }
    float vals[4][8];
#pragma unroll
    for (int j = 0; j < 8; j++) {
        unpack2(acc2[0][j], vals[0][j], vals[1][j]);
        unpack2(acc2[1][j], vals[2][j], vals[3][j]);
    }
#pragma unroll
    for (int i = 0; i < 4; i++) {
        int row = node0 + r * 4 + i;
        if (row >= NN) continue;
        float o[8];
#pragma unroll
        for (int j = 0; j < 8; j++) o[j] = fmaxf(vals[i][j] * sc[j] + bt[j], 0.f);
        float4 o0 = make_float4(o[0], o[1], o[2], o[3]);
        float4 o1 = make_float4(o[4], o[5], o[6], o[7]);
        size_t off = (size_t)row * HD + c * 8;
        *(float4*)(g_h + off)     = o0;
        *(float4*)(g_h + off + 4) = o1;
        if (write_z) {
            *(float4*)(g_z + off)     = o0;
            *(float4*)(g_z + off + 4) = o1;
        }
    }
}

// ---------------- pooling ----------------------------------------------------
__global__ void zero_pool_kernel() {
    int i = blockIdx.x * blockDim.x + threadIdx.x;
    float4 z = {0.f, 0.f, 0.f, 0.f};
    if (i < NG * HD / 4) ((float4*)g_sums)[i] = z;
    if (i < NG / 4) ((float4*)g_cnt)[i] = z;
}

__global__ void pool_kernel(const int* __restrict__ batch) {
    const int lane = threadIdx.x & 31, warp = threadIdx.x >> 5;
    const int n0 = (blockIdx.x * 8 + warp) * 32;
    if (n0 >= NN) return;
    const int nend = min(n0 + 32, NN);
    int curg = batch[n0];
    float4 acc = {0.f, 0.f, 0.f, 0.f};
    float cntv = 0.f;
    for (int n = n0; n < nend; n++) {
        int g = batch[n];
        if (g != curg) {
            red_add_v4(g_sums + (size_t)curg * HD + lane * 4, acc);
            if (lane == 0) atomicAdd(&g_cnt[curg], cntv);
            curg = g; acc = make_float4(0.f, 0.f, 0.f, 0.f); cntv = 0.f;
        }
        float4 hv = *(const float4*)(g_h + (size_t)n * HD + lane * 4);
        acc.x += hv.x; acc.y += hv.y; acc.z += hv.z; acc.w += hv.w;
        cntv += 1.f;
    }
    red_add_v4(g_sums + (size_t)curg * HD + lane * 4, acc);
    if (lane == 0) atomicAdd(&g_cnt[curg], cntv);
}

// ---------------- head: sigmoid(relu(p@Wh1+bh1)@Wh2+bh2) ----------------------
__global__ void head_kernel(const float* __restrict__ Wh1, const float* __restrict__ bh1,
                            const float* __restrict__ Wh2, const float* __restrict__ bh2,
                            float* __restrict__ out) {
    const int g = blockIdx.x, j = threadIdx.x;   // 64 threads
    __shared__ float ps[HD];
    __shared__ float redv[2];
    float rc = 1.0f / fmaxf(g_cnt[g], 1.0f);
    ps[j]      = g_sums[g * HD + j] * rc;
    ps[j + 64] = g_sums[g * HD + 64 + j] * rc;
    __syncthreads();
    float t = bh1[j];
#pragma unroll 8
    for (int k = 0; k < HD; k++) t += ps[k] * Wh1[k * 64 + j];
    t = fmaxf(t, 0.f) * Wh2[j];
#pragma unroll
    for (int o = 16; o > 0; o >>= 1) t += __shfl_down_sync(0xffffffffu, t, o);
    if ((j & 31) == 0) redv[j >> 5] = t;
    __syncthreads();
    if (j == 0) {
        float zv = redv[0] + redv[1] + bh2[0];
        out[g] = 1.0f / (1.0f + __expf(-zv));
    }
}

// ---------------- launch ------------------------------------------------------
extern "C" void kernel_launch(void* const* d_in, const int* in_sizes, int n_in,
                              void* d_out, int out_size) {
    const float* x      = (const float*)d_in[0];
    const int*   eidx   = (const int*)d_in[1];
    const float* eattr  = (const float*)d_in[2];
    const int*   batch  = (const int*)d_in[3];
    const float* W_enc  = (const float*)d_in[4];
    const float* b_enc  = (const float*)d_in[5];
    const float* We     = (const float*)d_in[6];
    const float* be     = (const float*)d_in[7];
    const float* W1     = (const float*)d_in[8];
    const float* b1     = (const float*)d_in[9];
    const float* W2     = (const float*)d_in[10];
    const float* b2     = (const float*)d_in[11];
    const float* gamma  = (const float*)d_in[12];
    const float* beta   = (const float*)d_in[13];
    const float* Wh1    = (const float*)d_in[14];
    const float* bh1    = (const float*)d_in[15];
    const float* Wh2    = (const float*)d_in[16];
    const float* bh2    = (const float*)d_in[17];
    float* out = (float*)d_out;

    const int enc_smem = (78 * HD + 78 * ENT) * 4;              // 59904 B
    const int mlp_smem = (HD * 2 * HD + HD * MNT) * 4;          // 196608 B
    cudaFuncSetAttribute(encoder_kernel, cudaFuncAttributeMaxDynamicSharedMemorySize, enc_smem);
    cudaFuncSetAttribute(node_mlp_kernel, cudaFuncAttributeMaxDynamicSharedMemorySize, mlp_smem);

    encoder_kernel<<<NN / ENT, 128, enc_smem>>>(x, W_enc, b_enc);

    const int* src = eidx;
    const int* dst = eidx + NE;
    const int mlp_grid = (NN + MNT - 1) / MNT;
    for (int l = 0; l < 3; l++) {
        edge_kernel<<<NE / (8 * EPW), 256>>>(src, dst, eattr,
                                             We + (size_t)l * 10 * HD, be + (size_t)l * HD);
        node_mlp_kernel<<<mlp_grid, 512, mlp_smem>>>(W1 + (size_t)l * HD * HD, b1 + (size_t)l * HD,
                                                     W2 + (size_t)l * HD * HD, b2 + (size_t)l * HD,
                                                     gamma + (size_t)l * HD, beta + (size_t)l * HD,
                                                     l < 2 ? 1 : 0);
    }
    zero_pool_kernel<<<(NG * HD / 4 + 255) / 256, 256>>>();
    pool_kernel<<<(NN + 255) / 256, 256>>>(batch);
    head_kernel<<<NG, 64>>>(Wh1, bh1, Wh2, bh2, out);
}

// round 13
// speedup vs baseline: 2.8342x; 2.8342x over previous
#include <cuda_runtime.h>
#include <math.h>

#define NN 200000
#define NE 800000
#define NG 8192
#define HD 128
#define ENT 64          // nodes per block tile: encoder
#define MNT 256         // nodes per block tile: node MLP

// ---------------- scratch (static device allocations; no cudaMalloc) ----------
__device__ float g_h[(size_t)NN * HD];     // node features          (~102 MB)
__device__ float g_z[(size_t)NN * HD];     // h + scattered messages (~102 MB)
__device__ float g_sums[NG * HD];          // pooled sums
__device__ float g_cnt[NG];                // pooled counts

__device__ __forceinline__ void red_add_v4(float* p, float4 v) {
    asm volatile("red.global.add.v4.f32 [%0], {%1,%2,%3,%4};"
                 :: "l"(p), "f"(v.x), "f"(v.y), "f"(v.z), "f"(v.w) : "memory");
}

// ---------------- encoder: h = x @ W_enc + b_enc  (K=78); writes g_h AND g_z --
__global__ void __launch_bounds__(128, 1)
encoder_kernel(const float* __restrict__ x,
               const float* __restrict__ W,
               const float* __restrict__ b) {
    extern __shared__ float sm[];
    float* Ws = sm;              // 78*128
    float* xt = Ws + 78 * HD;    // 78*ENT, k-major
    const int tid = threadIdx.x;
    const int node0 = blockIdx.x * ENT;

    const float4* Wg4 = (const float4*)W;
    float4* Ws4 = (float4*)Ws;
    for (int i = tid; i < 78 * (HD / 4); i += 128) Ws4[i] = Wg4[i];
    for (int idx = tid; idx < 78 * ENT; idx += 128) {
        int m = idx / 78, k = idx - m * 78;
        xt[k * ENT + m] = x[(size_t)(node0 + m) * 78 + k];
    }
    __syncthreads();

    const int r = tid >> 4, c = tid & 15;
    float acc[8][8];
#pragma unroll
    for (int j = 0; j < 8; j++) {
        float bb = b[c * 8 + j];
#pragma unroll
        for (int i = 0; i < 8; i++) acc[i][j] = bb;
    }
#pragma unroll 2
    for (int k = 0; k < 78; k++) {
        float4 a0 = *(float4*)&xt[k * ENT + r * 8];
        float4 a1 = *(float4*)&xt[k * ENT + r * 8 + 4];
        float4 w0 = *(float4*)&Ws[k * HD + c * 8];
        float4 w1 = *(float4*)&Ws[k * HD + c * 8 + 4];
        float a[8] = {a0.x, a0.y, a0.z, a0.w, a1.x, a1.y, a1.z, a1.w};
        float w[8] = {w0.x, w0.y, w0.z, w0.w, w1.x, w1.y, w1.z, w1.w};
#pragma unroll
        for (int i = 0; i < 8; i++)
#pragma unroll
            for (int j = 0; j < 8; j++) acc[i][j] += a[i] * w[j];
    }
#pragma unroll
    for (int i = 0; i < 8; i++) {
        float4 o0 = {acc[i][0], acc[i][1], acc[i][2], acc[i][3]};
        float4 o1 = {acc[i][4], acc[i][5], acc[i][6], acc[i][7]};
        size_t off = (size_t)(node0 + r * 8 + i) * HD + c * 8;
        *(float4*)(g_h + off)     = o0;
        *(float4*)(g_h + off + 4) = o1;
        *(float4*)(g_z + off)     = o0;   // pre-init scatter accumulator
        *(float4*)(g_z + off + 4) = o1;
    }
}

// ---------------- edge: m = relu(h[src] + ea@We + be); red-add into z[dst] ----
// R4 form: We read from shared per edge (32 regs, ~90% occupancy — measured
// faster than the register-hoisted variant which capped occupancy).
#define EPW 16
__global__ void edge_kernel(const int* __restrict__ src, const int* __restrict__ dst,
                            const float* __restrict__ ea,
                            const float* __restrict__ We, const float* __restrict__ be) {
    __shared__ float Wes[10 * HD];
    __shared__ float bes[HD];
    for (int i = threadIdx.x; i < 10 * HD; i += 256) Wes[i] = We[i];
    if (threadIdx.x < HD) bes[threadIdx.x] = be[threadIdx.x];
    __syncthreads();

    const int lane = threadIdx.x & 31;
    const int warp = threadIdx.x >> 5;
    const int e0 = (blockIdx.x * 8 + warp) * EPW;
    const float4 bev = *(const float4*)&bes[lane * 4];
    const float4* We4 = (const float4*)Wes;

    for (int t = 0; t < EPW; t++) {
        int e = e0 + t;
        if (e >= NE) break;
        float av = (lane < 10) ? ea[(size_t)e * 10 + lane] : 0.f;
        float4 acc = bev;
#pragma unroll
        for (int k = 0; k < 10; k++) {
            float a = __shfl_sync(0xffffffffu, av, k);
            float4 w = We4[k * 32 + lane];
            acc.x += a * w.x; acc.y += a * w.y; acc.z += a * w.z; acc.w += a * w.w;
        }
        int s = src[e], d = dst[e];
        float4 hv = *(const float4*)(g_h + (size_t)s * HD + lane * 4);
        float4 m;
        m.x = fmaxf(hv.x + acc.x, 0.f);
        m.y = fmaxf(hv.y + acc.y, 0.f);
        m.z = fmaxf(hv.z + acc.z, 0.f);
        m.w = fmaxf(hv.w + acc.w, 0.f);
        red_add_v4(g_z + (size_t)d * HD + lane * 4, m);
    }
}

// ---------------- node MLP: h = relu(BN(relu(z@W1+b1)@W2+b2)) -----------------
// 512 threads, 256-node tile, 8x8 micro-tiles; single W buffer reloaded.
__global__ void __launch_bounds__(512, 1)
node_mlp_kernel(const float* __restrict__ W1, const float* __restrict__ b1,
                const float* __restrict__ W2, const float* __restrict__ b2,
                const float* __restrict__ gamma, const float* __restrict__ beta,
                int write_z) {
    extern __shared__ float sm[];
    float* Ws = sm;               // 128*128 (W1, then W2)
    float* zt = sm + 16384;       // 128*MNT (k-major), reused for t-tile
    const int tid = threadIdx.x;
    const int node0 = blockIdx.x * MNT;

    const float4* W1g = (const float4*)W1;
    const float4* W2g = (const float4*)W2;
    for (int i = tid; i < 4096; i += 512) ((float4*)Ws)[i] = W1g[i];
    {   // stage z tile transposed (k-major); clamp rows past NN
        int k4 = tid & 31, m0 = tid >> 5;   // m0 in 0..15
        for (int mm = m0; mm < MNT; mm += 16) {
            int row = node0 + mm; if (row >= NN) row = NN - 1;
            float4 v = *(const float4*)(g_z + (size_t)row * HD + k4 * 4);
            zt[(k4 * 4 + 0) * MNT + mm] = v.x;
            zt[(k4 * 4 + 1) * MNT + mm] = v.y;
            zt[(k4 * 4 + 2) * MNT + mm] = v.z;
            zt[(k4 * 4 + 3) * MNT + mm] = v.w;
        }
    }
    __syncthreads();

    const int r = tid >> 4, c = tid & 15;   // 32 x 16 of 8x8 tiles -> 256x128
    float acc[8][8];
#pragma unroll
    for (int j = 0; j < 8; j++) {
        float bb = b1[c * 8 + j];
#pragma unroll
        for (int i = 0; i < 8; i++) acc[i][j] = bb;
    }
#pragma unroll 4
    for (int k = 0; k < HD; k++) {
        float4 a0 = *(float4*)&zt[k * MNT + r * 8];
        float4 a1 = *(float4*)&zt[k * MNT + r * 8 + 4];
        float4 w0 = *(float4*)&Ws[k * HD + c * 8];
        float4 w1 = *(float4*)&Ws[k * HD + c * 8 + 4];
        float a[8] = {a0.x, a0.y, a0.z, a0.w, a1.x, a1.y, a1.z, a1.w};
        float w[8] = {w0.x, w0.y, w0.z, w0.w, w1.x, w1.y, w1.z, w1.w};
#pragma unroll
        for (int i = 0; i < 8; i++)
#pragma unroll
            for (int j = 0; j < 8; j++) acc[i][j] += a[i] * w[j];
    }
    __syncthreads();   // done reading zt and Ws(W1)
#pragma unroll
    for (int j = 0; j < 8; j++)
#pragma unroll
        for (int i = 0; i < 8; i++)
            zt[(c * 8 + j) * MNT + r * 8 + i] = fmaxf(acc[i][j], 0.f);
    for (int i = tid; i < 4096; i += 512) ((float4*)Ws)[i] = W2g[i];
    __syncthreads();

#pragma unroll
    for (int j = 0; j < 8; j++) {
        float bb = b2[c * 8 + j];
#pragma unroll
        for (int i = 0; i < 8; i++) acc[i][j] = bb;
    }
#pragma unroll 4
    for (int k = 0; k < HD; k++) {
        float4 a0 = *(float4*)&zt[k * MNT + r * 8];
        float4 a1 = *(float4*)&zt[k * MNT + r * 8 + 4];
        float4 w0 = *(float4*)&Ws[k * HD + c * 8];
        float4 w1 = *(float4*)&Ws[k * HD + c * 8 + 4];
        float a[8] = {a0.x, a0.y, a0.z, a0.w, a1.x, a1.y, a1.z, a1.w};
        float w[8] = {w0.x, w0.y, w0.z, w0.w, w1.x, w1.y, w1.z, w1.w};
#pragma unroll
        for (int i = 0; i < 8; i++)
#pragma unroll
            for (int j = 0; j < 8; j++) acc[i][j] += a[i] * w[j];
    }

    const float inv_std = rsqrtf(1.0f + 1e-5f);
    float sc[8], bt[8];
#pragma unroll
    for (int j = 0; j < 8; j++) {
        sc[j] = gamma[c * 8 + j] * inv_std;
        bt[j] = beta[c * 8 + j];
    }
#pragma unroll
    for (int i = 0; i < 8; i++) {
        int row = node0 + r * 8 + i;
        if (row >= NN) continue;
        float o[8];
#pragma unroll
        for (int j = 0; j < 8; j++) o[j] = fmaxf(acc[i][j] * sc[j] + bt[j], 0.f);
        float4 o0 = make_float4(o[0], o[1], o[2], o[3]);
        float4 o1 = make_float4(o[4], o[5], o[6], o[7]);
        size_t off = (size_t)row * HD + c * 8;
        *(float4*)(g_h + off)     = o0;
        *(float4*)(g_h + off + 4) = o1;
        if (write_z) {
            *(float4*)(g_z + off)     = o0;
            *(float4*)(g_z + off + 4) = o1;
        }
    }
}

// ---------------- pooling ----------------------------------------------------
__global__ void zero_pool_kernel() {
    int i = blockIdx.x * blockDim.x + threadIdx.x;
    float4 z = {0.f, 0.f, 0.f, 0.f};
    if (i < NG * HD / 4) ((float4*)g_sums)[i] = z;
    if (i < NG / 4) ((float4*)g_cnt)[i] = z;
}

__global__ void pool_kernel(const int* __restrict__ batch) {
    const int lane = threadIdx.x & 31, warp = threadIdx.x >> 5;
    const int n0 = (blockIdx.x * 8 + warp) * 32;
    if (n0 >= NN) return;
    const int nend = min(n0 + 32, NN);
    int curg = batch[n0];
    float4 acc = {0.f, 0.f, 0.f, 0.f};
    float cntv = 0.f;
    for (int n = n0; n < nend; n++) {
        int g = batch[n];
        if (g != curg) {
            red_add_v4(g_sums + (size_t)curg * HD + lane * 4, acc);
            if (lane == 0) atomicAdd(&g_cnt[curg], cntv);
            curg = g; acc = make_float4(0.f, 0.f, 0.f, 0.f); cntv = 0.f;
        }
        float4 hv = *(const float4*)(g_h + (size_t)n * HD + lane * 4);
        acc.x += hv.x; acc.y += hv.y; acc.z += hv.z; acc.w += hv.w;
        cntv += 1.f;
    }
    red_add_v4(g_sums + (size_t)curg * HD + lane * 4, acc);
    if (lane == 0) atomicAdd(&g_cnt[curg], cntv);
}

// ---------------- head: sigmoid(relu(p@Wh1+bh1)@Wh2+bh2) ----------------------
__global__ void head_kernel(const float* __restrict__ Wh1, const float* __restrict__ bh1,
                            const float* __restrict__ Wh2, const float* __restrict__ bh2,
                            float* __restrict__ out) {
    const int g = blockIdx.x, j = threadIdx.x;   // 64 threads
    __shared__ float ps[HD];
    __shared__ float redv[2];
    float rc = 1.0f / fmaxf(g_cnt[g], 1.0f);
    ps[j]      = g_sums[g * HD + j] * rc;
    ps[j + 64] = g_sums[g * HD + 64 + j] * rc;
    __syncthreads();
    float t = bh1[j];
#pragma unroll 8
    for (int k = 0; k < HD; k++) t += ps[k] * Wh1[k * 64 + j];
    t = fmaxf(t, 0.f) * Wh2[j];
#pragma unroll
    for (int o = 16; o > 0; o >>= 1) t += __shfl_down_sync(0xffffffffu, t, o);
    if ((j & 31) == 0) redv[j >> 5] = t;
    __syncthreads();
    if (j == 0) {
        float zv = redv[0] + redv[1] + bh2[0];
        out[g] = 1.0f / (1.0f + __expf(-zv));
    }
}

// ---------------- launch ------------------------------------------------------
extern "C" void kernel_launch(void* const* d_in, const int* in_sizes, int n_in,
                              void* d_out, int out_size) {
    const float* x      = (const float*)d_in[0];
    const int*   eidx   = (const int*)d_in[1];
    const float* eattr  = (const float*)d_in[2];
    const int*   batch  = (const int*)d_in[3];
    const float* W_enc  = (const float*)d_in[4];
    const float* b_enc  = (const float*)d_in[5];
    const float* We     = (const float*)d_in[6];
    const float* be     = (const float*)d_in[7];
    const float* W1     = (const float*)d_in[8];
    const float* b1     = (const float*)d_in[9];
    const float* W2     = (const float*)d_in[10];
    const float* b2     = (const float*)d_in[11];
    const float* gamma  = (const float*)d_in[12];
    const float* beta   = (const float*)d_in[13];
    const float* Wh1    = (const float*)d_in[14];
    const float* bh1    = (const float*)d_in[15];
    const float* Wh2    = (const float*)d_in[16];
    const float* bh2    = (const float*)d_in[17];
    float* out = (float*)d_out;

    const int enc_smem = (78 * HD + 78 * ENT) * 4;          // 59904 B
    const int mlp_smem = (HD * HD + HD * MNT) * 4;          // 196608 B
    cudaFuncSetAttribute(encoder_kernel, cudaFuncAttributeMaxDynamicSharedMemorySize, enc_smem);
    cudaFuncSetAttribute(node_mlp_kernel, cudaFuncAttributeMaxDynamicSharedMemorySize, mlp_smem);

    encoder_kernel<<<NN / ENT, 128, enc_smem>>>(x, W_enc, b_enc);

    const int* src = eidx;
    const int* dst = eidx + NE;
    const int mlp_grid = (NN + MNT - 1) / MNT;
    for (int l = 0; l < 3; l++) {
        edge_kernel<<<NE / (8 * EPW), 256>>>(src, dst, eattr,
                                             We + (size_t)l * 10 * HD, be + (size_t)l * HD);
        node_mlp_kernel<<<mlp_grid, 512, mlp_smem>>>(W1 + (size_t)l * HD * HD, b1 + (size_t)l * HD,
                                                     W2 + (size_t)l * HD * HD, b2 + (size_t)l * HD,
                                                     gamma + (size_t)l * HD, beta + (size_t)l * HD,
                                                     l < 2 ? 1 : 0);
    }
    zero_pool_kernel<<<(NG * HD / 4 + 255) / 256, 256>>>();
    pool_kernel<<<(NN + 255) / 256, 256>>>(batch);
    head_kernel<<<NG, 64>>>(Wh1, bh1, Wh2, bh2, out);
}

// round 17
// speedup vs baseline: 3.2207x; 1.1364x over previous
#include <cuda_runtime.h>
#include <math.h>

#define NN 200000
#define NE 800000
#define NG 8192
#define HD 128
#define ENT 64          // nodes per block tile: encoder
#define MNT 256         // nodes per block tile: node MLP

// ---------------- scratch (static device allocations; no cudaMalloc) ----------
__device__ float g_h[(size_t)NN * HD];     // node features          (~102 MB)
__device__ float g_z[(size_t)NN * HD];     // h + scattered messages (~102 MB)
__device__ float g_sums[NG * HD];          // pooled sums
__device__ float g_cnt[NG];                // pooled counts

__device__ __forceinline__ void red_add_v4(float* p, float4 v) {
    asm volatile("red.global.add.v4.f32 [%0], {%1,%2,%3,%4};"
                 :: "l"(p), "f"(v.x), "f"(v.y), "f"(v.z), "f"(v.w) : "memory");
}

// Swizzled k-major index into the zt tile: XOR at 8-float granularity keeps
// float4/float8 runs contiguous while spreading banks for strided writers.
__device__ __forceinline__ int zidx(int k, int m) {
    return k * MNT + ((((m >> 3) ^ (k >> 2)) & 31) << 3) + (m & 7);
}

// ---------------- encoder: h = x @ W_enc + b_enc  (K=78); writes g_h AND g_z --
__global__ void __launch_bounds__(128, 1)
encoder_kernel(const float* __restrict__ x,
               const float* __restrict__ W,
               const float* __restrict__ b) {
    extern __shared__ float sm[];
    float* Ws = sm;              // 78*128
    float* xt = Ws + 78 * HD;    // 78*ENT, k-major
    const int tid = threadIdx.x;
    const int node0 = blockIdx.x * ENT;

    const float4* Wg4 = (const float4*)W;
    float4* Ws4 = (float4*)Ws;
    for (int i = tid; i < 78 * (HD / 4); i += 128) Ws4[i] = Wg4[i];
    for (int idx = tid; idx < 78 * ENT; idx += 128) {
        int m = idx / 78, k = idx - m * 78;
        xt[k * ENT + m] = x[(size_t)(node0 + m) * 78 + k];
    }
    __syncthreads();

    const int r = tid >> 4, c = tid & 15;
    float acc[8][8];
#pragma unroll
    for (int j = 0; j < 8; j++) {
        float bb = b[c * 8 + j];
#pragma unroll
        for (int i = 0; i < 8; i++) acc[i][j] = bb;
    }
#pragma unroll 2
    for (int k = 0; k < 78; k++) {
        float4 a0 = *(float4*)&xt[k * ENT + r * 8];
        float4 a1 = *(float4*)&xt[k * ENT + r * 8 + 4];
        float4 w0 = *(float4*)&Ws[k * HD + c * 8];
        float4 w1 = *(float4*)&Ws[k * HD + c * 8 + 4];
        float a[8] = {a0.x, a0.y, a0.z, a0.w, a1.x, a1.y, a1.z, a1.w};
        float w[8] = {w0.x, w0.y, w0.z, w0.w, w1.x, w1.y, w1.z, w1.w};
#pragma unroll
        for (int i = 0; i < 8; i++)
#pragma unroll
            for (int j = 0; j < 8; j++) acc[i][j] += a[i] * w[j];
    }
#pragma unroll
    for (int i = 0; i < 8; i++) {
        float4 o0 = {acc[i][0], acc[i][1], acc[i][2], acc[i][3]};
        float4 o1 = {acc[i][4], acc[i][5], acc[i][6], acc[i][7]};
        size_t off = (size_t)(node0 + r * 8 + i) * HD + c * 8;
        *(float4*)(g_h + off)     = o0;
        *(float4*)(g_h + off + 4) = o1;
        *(float4*)(g_z + off)     = o0;   // pre-init scatter accumulator
        *(float4*)(g_z + off + 4) = o1;
    }
}

// ---------------- edge: m = relu(h[src] + ea@We + be); red-add into z[dst] ----
// R4 form (measured best: 32 regs, ~90% occupancy).
#define EPW 16
__global__ void edge_kernel(const int* __restrict__ src, const int* __restrict__ dst,
                            const float* __restrict__ ea,
                            const float* __restrict__ We, const float* __restrict__ be) {
    __shared__ float Wes[10 * HD];
    __shared__ float bes[HD];
    for (int i = threadIdx.x; i < 10 * HD; i += 256) Wes[i] = We[i];
    if (threadIdx.x < HD) bes[threadIdx.x] = be[threadIdx.x];
    __syncthreads();

    const int lane = threadIdx.x & 31;
    const int warp = threadIdx.x >> 5;
    const int e0 = (blockIdx.x * 8 + warp) * EPW;
    const float4 bev = *(const float4*)&bes[lane * 4];
    const float4* We4 = (const float4*)Wes;

    for (int t = 0; t < EPW; t++) {
        int e = e0 + t;
        if (e >= NE) break;
        float av = (lane < 10) ? ea[(size_t)e * 10 + lane] : 0.f;
        float4 acc = bev;
#pragma unroll
        for (int k = 0; k < 10; k++) {
            float a = __shfl_sync(0xffffffffu, av, k);
            float4 w = We4[k * 32 + lane];
            acc.x += a * w.x; acc.y += a * w.y; acc.z += a * w.z; acc.w += a * w.w;
        }
        int s = src[e], d = dst[e];
        float4 hv = *(const float4*)(g_h + (size_t)s * HD + lane * 4);
        float4 m;
        m.x = fmaxf(hv.x + acc.x, 0.f);
        m.y = fmaxf(hv.y + acc.y, 0.f);
        m.z = fmaxf(hv.z + acc.z, 0.f);
        m.w = fmaxf(hv.w + acc.w, 0.f);
        red_add_v4(g_z + (size_t)d * HD + lane * 4, m);
    }
}

// ---------------- node MLP: h = relu(BN(relu(z@W1+b1)@W2+b2)) -----------------
// 512 threads, 256-node tile, 8x8 micro-tiles; single W buffer reloaded.
// zt uses the zidx() XOR-swizzled k-major layout; staging lanes run along m
// (conflict-free STS) instead of along k (32-way conflicted).
__global__ void __launch_bounds__(512, 1)
node_mlp_kernel(const float* __restrict__ W1, const float* __restrict__ b1,
                const float* __restrict__ W2, const float* __restrict__ b2,
                const float* __restrict__ gamma, const float* __restrict__ beta,
                int write_z) {
    extern __shared__ float sm[];
    float* Ws = sm;               // 128*128 (W1, then W2)
    float* zt = sm + 16384;       // 128*MNT swizzled k-major, reused for t-tile
    const int tid = threadIdx.x;
    const int node0 = blockIdx.x * MNT;

    const float4* W1g = (const float4*)W1;
    const float4* W2g = (const float4*)W2;
    for (int i = tid; i < 4096; i += 512) ((float4*)Ws)[i] = W1g[i];
    {   // stage z tile: lanes along m -> conflict-free swizzled stores
        const int lane = tid & 31;      // m base
        const int wk = tid >> 5;        // 0..15 -> k4 chunks {wk, wk+16}
        for (int kk4 = wk; kk4 < 32; kk4 += 16) {
            for (int mm = lane; mm < MNT; mm += 32) {
                int row = node0 + mm; if (row >= NN) row = NN - 1;
                float4 v = *(const float4*)(g_z + (size_t)row * HD + kk4 * 4);
                zt[zidx(kk4 * 4 + 0, mm)] = v.x;
                zt[zidx(kk4 * 4 + 1, mm)] = v.y;
                zt[zidx(kk4 * 4 + 2, mm)] = v.z;
                zt[zidx(kk4 * 4 + 3, mm)] = v.w;
            }
        }
    }
    __syncthreads();

    const int r = tid >> 4, c = tid & 15;   // 32 x 16 of 8x8 tiles -> 256x128
    float acc[8][8];
#pragma unroll
    for (int j = 0; j < 8; j++) {
        float bb = b1[c * 8 + j];
#pragma unroll
        for (int i = 0; i < 8; i++) acc[i][j] = bb;
    }
#pragma unroll 4
    for (int k = 0; k < HD; k++) {
        const int ab = zidx(k, r * 8);
        float4 a0 = *(float4*)&zt[ab];
        float4 a1 = *(float4*)&zt[ab + 4];
        float4 w0 = *(float4*)&Ws[k * HD + c * 8];
        float4 w1 = *(float4*)&Ws[k * HD + c * 8 + 4];
        float a[8] = {a0.x, a0.y, a0.z, a0.w, a1.x, a1.y, a1.z, a1.w};
        float w[8] = {w0.x, w0.y, w0.z, w0.w, w1.x, w1.y, w1.z, w1.w};
#pragma unroll
        for (int i = 0; i < 8; i++)
#pragma unroll
            for (int j = 0; j < 8; j++) acc[i][j] += a[i] * w[j];
    }
    __syncthreads();   // done reading zt and Ws(W1)
#pragma unroll
    for (int j = 0; j < 8; j++) {
        const int tb = zidx(c * 8 + j, r * 8);
        *(float4*)&zt[tb] = make_float4(fmaxf(acc[0][j], 0.f), fmaxf(acc[1][j], 0.f),
                                        fmaxf(acc[2][j], 0.f), fmaxf(acc[3][j], 0.f));
        *(float4*)&zt[tb + 4] = make_float4(fmaxf(acc[4][j], 0.f), fmaxf(acc[5][j], 0.f),
                                            fmaxf(acc[6][j], 0.f), fmaxf(acc[7][j], 0.f));
    }
    for (int i = tid; i < 4096; i += 512) ((float4*)Ws)[i] = W2g[i];
    __syncthreads();

#pragma unroll
    for (int j = 0; j < 8; j++) {
        float bb = b2[c * 8 + j];
#pragma unroll
        for (int i = 0; i < 8; i++) acc[i][j] = bb;
    }
#pragma unroll 4
    for (int k = 0; k < HD; k++) {
        const int ab = zidx(k, r * 8);
        float4 a0 = *(float4*)&zt[ab];
        float4 a1 = *(float4*)&zt[ab + 4];
        float4 w0 = *(float4*)&Ws[k * HD + c * 8];
        float4 w1 = *(float4*)&Ws[k * HD + c * 8 + 4];
        float a[8] = {a0.x, a0.y, a0.z, a0.w, a1.x, a1.y, a1.z, a1.w};
        float w[8] = {w0.x, w0.y, w0.z, w0.w, w1.x, w1.y, w1.z, w1.w};
#pragma unroll
        for (int i = 0; i < 8; i++)
#pragma unroll
            for (int j = 0; j < 8; j++) acc[i][j] += a[i] * w[j];
    }

    const float inv_std = rsqrtf(1.0f + 1e-5f);
    float sc[8], bt[8];
#pragma unroll
    for (int j = 0; j < 8; j++) {
        sc[j] = gamma[c * 8 + j] * inv_std;
        bt[j] = beta[c * 8 + j];
    }
#pragma unroll
    for (int i = 0; i < 8; i++) {
        int row = node0 + r * 8 + i;
        if (row >= NN) continue;
        float o[8];
#pragma unroll
        for (int j = 0; j < 8; j++) o[j] = fmaxf(acc[i][j] * sc[j] + bt[j], 0.f);
        float4 o0 = make_float4(o[0], o[1], o[2], o[3]);
        float4 o1 = make_float4(o[4], o[5], o[6], o[7]);
        size_t off = (size_t)row * HD + c * 8;
        *(float4*)(g_h + off)     = o0;
        *(float4*)(g_h + off + 4) = o1;
        if (write_z) {
            *(float4*)(g_z + off)     = o0;
            *(float4*)(g_z + off + 4) = o1;
        }
    }
}

// ---------------- pooling ----------------------------------------------------
__global__ void zero_pool_kernel() {
    int i = blockIdx.x * blockDim.x + threadIdx.x;
    float4 z = {0.f, 0.f, 0.f, 0.f};
    if (i < NG * HD / 4) ((float4*)g_sums)[i] = z;
    if (i < NG / 4) ((float4*)g_cnt)[i] = z;
}

__global__ void pool_kernel(const int* __restrict__ batch) {
    const int lane = threadIdx.x & 31, warp = threadIdx.x >> 5;
    const int n0 = (blockIdx.x * 8 + warp) * 32;
    if (n0 >= NN) return;
    const int nend = min(n0 + 32, NN);
    int curg = batch[n0];
    float4 acc = {0.f, 0.f, 0.f, 0.f};
    float cntv = 0.f;
    for (int n = n0; n < nend; n++) {
        int g = batch[n];
        if (g != curg) {
            red_add_v4(g_sums + (size_t)curg * HD + lane * 4, acc);
            if (lane == 0) atomicAdd(&g_cnt[curg], cntv);
            curg = g; acc = make_float4(0.f, 0.f, 0.f, 0.f); cntv = 0.f;
        }
        float4 hv = *(const float4*)(g_h + (size_t)n * HD + lane * 4);
        acc.x += hv.x; acc.y += hv.y; acc.z += hv.z; acc.w += hv.w;
        cntv += 1.f;
    }
    red_add_v4(g_sums + (size_t)curg * HD + lane * 4, acc);
    if (lane == 0) atomicAdd(&g_cnt[curg], cntv);
}

// ---------------- head: sigmoid(relu(p@Wh1+bh1)@Wh2+bh2) ----------------------
__global__ void head_kernel(const float* __restrict__ Wh1, const float* __restrict__ bh1,
                            const float* __restrict__ Wh2, const float* __restrict__ bh2,
                            float* __restrict__ out) {
    const int g = blockIdx.x, j = threadIdx.x;   // 64 threads
    __shared__ float ps[HD];
    __shared__ float redv[2];
    float rc = 1.0f / fmaxf(g_cnt[g], 1.0f);
    ps[j]      = g_sums[g * HD + j] * rc;
    ps[j + 64] = g_sums[g * HD + 64 + j] * rc;
    __syncthreads();
    float t = bh1[j];
#pragma unroll 8
    for (int k = 0; k < HD; k++) t += ps[k] * Wh1[k * 64 + j];
    t = fmaxf(t, 0.f) * Wh2[j];
#pragma unroll
    for (int o = 16; o > 0; o >>= 1) t += __shfl_down_sync(0xffffffffu, t, o);
    if ((j & 31) == 0) redv[j >> 5] = t;
    __syncthreads();
    if (j == 0) {
        float zv = redv[0] + redv[1] + bh2[0];
        out[g] = 1.0f / (1.0f + __expf(-zv));
    }
}

// ---------------- launch ------------------------------------------------------
extern "C" void kernel_launch(void* const* d_in, const int* in_sizes, int n_in,
                              void* d_out, int out_size) {
    const float* x      = (const float*)d_in[0];
    const int*   eidx   = (const int*)d_in[1];
    const float* eattr  = (const float*)d_in[2];
    const int*   batch  = (const int*)d_in[3];
    const float* W_enc  = (const float*)d_in[4];
    const float* b_enc  = (const float*)d_in[5];
    const float* We     = (const float*)d_in[6];
    const float* be     = (const float*)d_in[7];
    const float* W1     = (const float*)d_in[8];
    const float* b1     = (const float*)d_in[9];
    const float* W2     = (const float*)d_in[10];
    const float* b2     = (const float*)d_in[11];
    const float* gamma  = (const float*)d_in[12];
    const float* beta   = (const float*)d_in[13];
    const float* Wh1    = (const float*)d_in[14];
    const float* bh1    = (const float*)d_in[15];
    const float* Wh2    = (const float*)d_in[16];
    const float* bh2    = (const float*)d_in[17];
    float* out = (float*)d_out;

    const int enc_smem = (78 * HD + 78 * ENT) * 4;          // 59904 B
    const int mlp_smem = (HD * HD + HD * MNT) * 4;          // 196608 B
    cudaFuncSetAttribute(encoder_kernel, cudaFuncAttributeMaxDynamicSharedMemorySize, enc_smem);
    cudaFuncSetAttribute(node_mlp_kernel, cudaFuncAttributeMaxDynamicSharedMemorySize, mlp_smem);

    encoder_kernel<<<NN / ENT, 128, enc_smem>>>(x, W_enc, b_enc);

    const int* src = eidx;
    const int* dst = eidx + NE;
    const int mlp_grid = (NN + MNT - 1) / MNT;
    for (int l = 0; l < 3; l++) {
        edge_kernel<<<NE / (8 * EPW), 256>>>(src, dst, eattr,
                                             We + (size_t)l * 10 * HD, be + (size_t)l * HD);
        node_mlp_kernel<<<mlp_grid, 512, mlp_smem>>>(W1 + (size_t)l * HD * HD, b1 + (size_t)l * HD,
                                                     W2 + (size_t)l * HD * HD, b2 + (size_t)l * HD,
                                                     gamma + (size_t)l * HD, beta + (size_t)l * HD,
                                                     l < 2 ? 1 : 0);
    }
    zero_pool_kernel<<<(NG * HD / 4 + 255) / 256, 256>>>();
    pool_kernel<<<(NN + 255) / 256, 256>>>(batch);
    head_kernel<<<NG, 64>>>(Wh1, bh1, Wh2, bh2, out);
}